// round 3
// baseline (speedup 1.0000x reference)
#include <cuda_runtime.h>

#define S 64
#define P 2048
#define C 32
#define A 2048
#define D 128
#define E 64
#define E2 32

#define SPLITS 2
#define PH (P / SPLITS)      // 1024
#define TILE 128
#define NTILES (PH / TILE)   // 8
#define G 2                  // agent-group slots per (scene, half)

typedef unsigned long long ull;

__device__ __forceinline__ ull pack2(float lo, float hi) {
    ull r; asm("mov.b64 %0,{%1,%2};" : "=l"(r) : "f"(lo), "f"(hi)); return r;
}
__device__ __forceinline__ void unpack2(ull v, float& lo, float& hi) {
    asm("mov.b64 {%0,%1},%2;" : "=f"(lo), "=f"(hi) : "l"(v));
}
__device__ __forceinline__ ull fma2(ull a, ull b, ull c) {
    ull d; asm("fma.rn.f32x2 %0,%1,%2,%3;" : "=l"(d) : "l"(a), "l"(b), "l"(c)); return d;
}
__device__ __forceinline__ ull add2(ull a, ull b) {
    ull d; asm("add.rn.f32x2 %0,%1,%2;" : "=l"(d) : "l"(a), "l"(b)); return d;
}
__device__ __forceinline__ ull mul2(ull a, ull b) {
    ull d; asm("mul.rn.f32x2 %0,%1,%2;" : "=l"(d) : "l"(a), "l"(b)); return d;
}
__device__ __forceinline__ ull relu2(ull v) {
    float lo, hi; unpack2(v, lo, hi);
    return pack2(fmaxf(lo, 0.f), fmaxf(hi, 0.f));
}

// global scratch
__device__ ull   g_att2u[A * E2];
__device__ int   g_alist[S * A];
__device__ int   g_cnt[S];
__device__ float g_pm[A * SPLITS];
__device__ float g_pl[A * SPLITS];
__device__ float g_pacc[A * SPLITS * C];

// ---------------------------------------------------------------------------
// Deterministic per-scene agent lists (ballot compaction, stable order).
// ---------------------------------------------------------------------------
__global__ __launch_bounds__(256) void k_group(const int* __restrict__ sidx) {
    int s = blockIdx.x, tid = threadIdx.x, wid = tid >> 5, lane = tid & 31;
    __shared__ int wcnt[8];
    int base = 0;
#pragma unroll
    for (int r = 0; r < A / 256; r++) {
        int a = r * 256 + tid;
        bool p = (sidx[a] == s);
        unsigned bal = __ballot_sync(0xffffffffu, p);
        if (lane == 0) wcnt[wid] = __popc(bal);
        __syncthreads();
        int woff = 0, tot = 0;
#pragma unroll
        for (int w = 0; w < 8; w++) { int c = wcnt[w]; if (w < wid) woff += c; tot += c; }
        if (p) g_alist[s * A + base + woff + __popc(bal & ((1u << lane) - 1u))] = a;
        base += tot;
        __syncthreads();
    }
    if (tid == 0) g_cnt[s] = base;
}

// ---------------------------------------------------------------------------
// att2[a] = b_df + dyn[a] @ W_df   (8 agents/block, packed f32x2)
// ---------------------------------------------------------------------------
__global__ __launch_bounds__(256) void k_att2(const float* __restrict__ dyn,
                                              const float* __restrict__ Wdf,
                                              const float* __restrict__ bdf) {
    __shared__ ull   Wp[D * E2];        // 32 KB, raw ull copy of [c][e] pairs
    __shared__ float dyn_s[8 * D];      // 4 KB
    int tid = threadIdx.x;
    int a0 = blockIdx.x * 8;
    const ull* Wsrc = (const ull*)Wdf;
    for (int i = tid; i < D * E2; i += 256) Wp[i] = Wsrc[i];
    ((float4*)dyn_s)[tid] = ((const float4*)(dyn + (size_t)a0 * D))[tid];
    __syncthreads();

    int aa = tid >> 5, e2 = tid & 31;
    ull acc = ((const ull*)bdf)[e2];
    const float* dr = dyn_s + aa * D;
#pragma unroll 8
    for (int c = 0; c < D; c++) {
        float d = dr[c];
        acc = fma2(pack2(d, d), Wp[c * E2 + e2], acc);
    }
    g_att2u[(size_t)(a0 + aa) * E2 + e2] = acc;
}

// dynamic smem layout (bytes), 8-aligned
#define OFF_ATT1 0                       // ull[32*128]   32768
#define OFF_ATT2 32768                   // ull[32*32]     8192
#define OFF_WEXP 40960                   // ull[8*2*128]  16384
#define OFF_WSN  57344                   // ull[32*32]     8192
#define OFF_WFC  65536                   // ull[32]         256
#define OFF_BSN  65792                   // ull[32]         256
#define OFF_GST  66048                   // float[32*129] 16512
#define SMEM_BYTES 82560

// one chunk: 4 agents per warp over a 128-pixel tile
__device__ __forceinline__ void process_chunk(
    const ull* __restrict__ att1p, const ull* __restrict__ att2p,
    ull* __restrict__ wexp2w, const float* __restrict__ gs_sT,
    const ull* __restrict__ wfcp, int wid, int lane,
    float* m, float* l, ull* accp)
{
    const int base = wid * 4;
    ull pl[16];
#pragma unroll
    for (int k = 0; k < 16; k++) pl[k] = 0ull;

#pragma unroll 4
    for (int e2 = 0; e2 < E2; e2++) {
        ull a0 = att1p[e2 * TILE + 0 * 32 + lane];
        ull a1 = att1p[e2 * TILE + 1 * 32 + lane];
        ull a2 = att1p[e2 * TILE + 2 * 32 + lane];
        ull a3 = att1p[e2 * TILE + 3 * 32 + lane];
        ull w2 = wfcp[e2];
#pragma unroll
        for (int i = 0; i < 4; i++) {
            ull b = att2p[(base + i) * E2 + e2];
            pl[i * 4 + 0] = fma2(relu2(add2(a0, b)), w2, pl[i * 4 + 0]);
            pl[i * 4 + 1] = fma2(relu2(add2(a1, b)), w2, pl[i * 4 + 1]);
            pl[i * 4 + 2] = fma2(relu2(add2(a2, b)), w2, pl[i * 4 + 2]);
            pl[i * 4 + 3] = fma2(relu2(add2(a3, b)), w2, pl[i * 4 + 3]);
        }
    }

    float w[4][4], sc[4];
#pragma unroll
    for (int i = 0; i < 4; i++) {
        float lw[4];
#pragma unroll
        for (int sub = 0; sub < 4; sub++) {
            float lo, hi; unpack2(pl[i * 4 + sub], lo, hi);
            lw[sub] = lo + hi;
        }
        float tm = fmaxf(fmaxf(lw[0], lw[1]), fmaxf(lw[2], lw[3]));
#pragma unroll
        for (int o = 16; o > 0; o >>= 1)
            tm = fmaxf(tm, __shfl_xor_sync(0xffffffffu, tm, o));
        float mo = m[i];
        float mn = fmaxf(mo, tm);
        sc[i] = __expf(mo - mn);
        float ws = 0.f;
#pragma unroll
        for (int sub = 0; sub < 4; sub++) {
            w[i][sub] = __expf(lw[sub] - mn);
            ws += w[i][sub];
        }
#pragma unroll
        for (int o = 16; o > 0; o >>= 1)
            ws += __shfl_xor_sync(0xffffffffu, ws, o);
        l[i] = l[i] * sc[i] + ws;
        m[i] = mn;
    }
#pragma unroll
    for (int pr = 0; pr < 2; pr++) {
        accp[pr] = mul2(accp[pr], pack2(sc[pr * 2], sc[pr * 2 + 1]));
#pragma unroll
        for (int sub = 0; sub < 4; sub++)
            wexp2w[pr * TILE + sub * 32 + lane] =
                pack2(w[pr * 2][sub], w[pr * 2 + 1][sub]);
    }
    __syncwarp();

#pragma unroll 4
    for (int p = 0; p < TILE; p++) {
        float g = gs_sT[lane * 129 + p];
        ull gg = pack2(g, g);
        accp[0] = fma2(wexp2w[p], gg, accp[0]);
        accp[1] = fma2(wexp2w[TILE + p], gg, accp[1]);
    }
    __syncwarp();
}

// ---------------------------------------------------------------------------
// block = (scene, half, group-of-<=32-agents)
// ---------------------------------------------------------------------------
__global__ __launch_bounds__(256, 2) void k_attn(const float* __restrict__ gs,
                                                 const float* __restrict__ wfc,
                                                 const float* __restrict__ Wsn,
                                                 const float* __restrict__ bsn) {
    extern __shared__ char smraw[];
    ull*   att1p = (ull*)(smraw + OFF_ATT1);
    ull*   att2p = (ull*)(smraw + OFF_ATT2);
    ull*   wexp2 = (ull*)(smraw + OFF_WEXP);
    ull*   Wsnp  = (ull*)(smraw + OFF_WSN);
    ull*   wfcp  = (ull*)(smraw + OFF_WFC);
    ull*   bsnp  = (ull*)(smraw + OFF_BSN);
    float* gs_sT = (float*)(smraw + OFF_GST);

    int tid = threadIdx.x;
    int wid = tid >> 5, lane = tid & 31;
    int sblk = blockIdx.x >> 2;
    int half = (blockIdx.x >> 1) & 1;
    int grp  = blockIdx.x & 1;

    const int nA = g_cnt[sblk];
    const int start = grp * 32;
    if (start >= nA) return;
    const int end = (grp == G - 1) ? nA : (nA < 32 ? nA : 32);
    const int p0 = half * PH;

    for (int i = tid; i < C * E; i += 256) ((float*)Wsnp)[i] = Wsn[i];
    if (tid < E) { ((float*)wfcp)[tid] = wfc[tid]; ((float*)bsnp)[tid] = bsn[tid]; }

    ull* wexp2w = wexp2 + wid * (2 * TILE);
    const int* alist = g_alist + sblk * A;

    for (int c0 = start; c0 < end; c0 += 32) {
        // stage att2 for this chunk (clamped duplicates for padding)
        for (int idx = tid; idx < 32 * E2; idx += 256) {
            int j = idx >> 5, e2 = idx & 31;
            int src = c0 + j; if (src >= end) src = end - 1;
            att2p[idx] = g_att2u[(size_t)alist[src] * E2 + e2];
        }

        float m[4], l[4]; ull accp[2];
#pragma unroll
        for (int k = 0; k < 4; k++) { m[k] = -1e30f; l[k] = 0.f; }
        accp[0] = accp[1] = 0ull;

        // prefetch tile 0
        float4 pf[4];
        {
            const float4* src = (const float4*)(gs + (size_t)(sblk * P + p0) * C);
#pragma unroll
            for (int k = 0; k < 4; k++) pf[k] = src[tid + k * 256];
        }
        __syncthreads();   // att2p + consts ready; prior chunk readers done

        for (int t = 0; t < NTILES; t++) {
            // store prefetched gs tile transposed [c][p]
#pragma unroll
            for (int k = 0; k < 4; k++) {
                int r = tid + k * 256;
                int px = r >> 3, c4 = (r & 7) * 4;
                gs_sT[(c4 + 0) * 129 + px] = pf[k].x;
                gs_sT[(c4 + 1) * 129 + px] = pf[k].y;
                gs_sT[(c4 + 2) * 129 + px] = pf[k].z;
                gs_sT[(c4 + 3) * 129 + px] = pf[k].w;
            }
            __syncthreads();
            // prefetch next tile (latency hidden behind att1 + chunk)
            if (t + 1 < NTILES) {
                const float4* src = (const float4*)(
                    gs + (size_t)(sblk * P + p0 + (t + 1) * TILE) * C);
#pragma unroll
                for (int k = 0; k < 4; k++) pf[k] = src[tid + k * 256];
            }
            // att1: att1p[e2][p] = bsn + sum_c gs[p][c] * Wsn[c][e-pair]
            {
                int p = tid & 127, eh = tid >> 7;
                ull acc[16];
#pragma unroll
                for (int e2 = 0; e2 < 16; e2++) acc[e2] = bsnp[eh * 16 + e2];
#pragma unroll 4
                for (int c = 0; c < C; c++) {
                    float gv = gs_sT[c * 129 + p];
                    ull gg = pack2(gv, gv);
#pragma unroll
                    for (int e2 = 0; e2 < 16; e2++)
                        acc[e2] = fma2(gg, Wsnp[c * E2 + eh * 16 + e2], acc[e2]);
                }
#pragma unroll
                for (int e2 = 0; e2 < 16; e2++)
                    att1p[(eh * 16 + e2) * TILE + p] = acc[e2];
            }
            __syncthreads();

            process_chunk(att1p, att2p, wexp2w, gs_sT, wfcp, wid, lane, m, l, accp);
            __syncthreads();   // gs_sT/att1p free for next tile
        }

        // write partials
#pragma unroll
        for (int i = 0; i < 4; i++) {
            int idx = c0 + wid * 4 + i;
            if (idx < end) {
                int a = alist[idx];
                float lo, hi; unpack2(accp[i / 2], lo, hi);
                g_pacc[(size_t)(a * SPLITS + half) * C + lane] = (i & 1) ? hi : lo;
                if (lane == 0) {
                    g_pm[a * SPLITS + half] = m[i];
                    g_pl[a * SPLITS + half] = l[i];
                }
            }
        }
    }
}

// ---------------------------------------------------------------------------
__global__ __launch_bounds__(256) void k_combine(float* __restrict__ out) {
    int gwarp = (blockIdx.x * blockDim.x + threadIdx.x) >> 5;
    int lane = threadIdx.x & 31;
    if (gwarp >= A) return;
    int a = gwarp;
    float m0 = g_pm[a * 2], m1 = g_pm[a * 2 + 1];
    float l0 = g_pl[a * 2], l1 = g_pl[a * 2 + 1];
    float M = fmaxf(m0, m1);
    float s0 = __expf(m0 - M), s1 = __expf(m1 - M);
    float L = l0 * s0 + l1 * s1;
    out[a * C + lane] = (g_pacc[(size_t)(a * 2) * C + lane] * s0 +
                         g_pacc[(size_t)(a * 2 + 1) * C + lane] * s1) / L;
}

// ---------------------------------------------------------------------------
extern "C" void kernel_launch(void* const* d_in, const int* in_sizes, int n_in,
                              void* d_out, int out_size) {
    const float* gs   = (const float*)d_in[0];
    const int*   sidx = (const int*)d_in[1];
    const float* dyn  = (const float*)d_in[2];
    const float* Wsn  = (const float*)d_in[3];
    const float* bsn  = (const float*)d_in[4];
    const float* Wdf  = (const float*)d_in[5];
    const float* bdf  = (const float*)d_in[6];
    const float* wfc  = (const float*)d_in[7];
    float* out = (float*)d_out;

    k_group<<<S, 256>>>(sidx);
    k_att2<<<A / 8, 256>>>(dyn, Wdf, bdf);

    cudaFuncSetAttribute(k_attn, cudaFuncAttributeMaxDynamicSharedMemorySize,
                         SMEM_BYTES);
    k_attn<<<S * SPLITS * G, 256, SMEM_BYTES>>>(gs, wfc, Wsn, bsn);

    k_combine<<<(A * 32) / 256, 256>>>(out);
}